// round 13
// baseline (speedup 1.0000x reference)
#include <cuda_runtime.h>

#define BN 8
#define JN 64
#define CN 32
#define CG 8               // channels per block group (grid.z = CN/CG = 4)
#define HT 8
#define HIMG_ 256
#define WIMG_ 256
#define HW (HIMG_*WIMG_)

// mask_mode: 0 = float mask after res, 1 = uint8 mask packed after res, 2 = no mask
__global__ void roirotate_kernel(const float* __restrict__ image,
                                 const float* __restrict__ boxes,
                                 float* __restrict__ out,
                                 int max_w, float inv_w, int mask_mode)
{
    const int bj = blockIdx.y;               // 0 .. B*J-1
    const int b  = bj >> 6;                  // JN = 64
    const int c0 = blockIdx.z * CG;

    const float* bx = boxes + bj * 5;
    float l   = bx[0];
    float t   = bx[1];
    float r   = bx[2];
    float btm = bx[3];

    float bw = r - l;
    float bh = btm - t;
    // widths = int32( (bw/bh) * 8 ) in float32 arithmetic — keep EXACT
    int width = (int)(__fmul_rn(__fdiv_rn(bw, bh), 8.0f));
    float each_w = bw / (float)(width - 1);
    float each_h = bh * (1.0f / 7.0f);        // HEIGHT-1 = 7

    const int chw = HT * max_w;               // per-channel output stride
    const float* imgb = image + (b * CN + c0) * HW;
    float* outb = out + (bj * CN + c0) * chw;

    // ---- mask (only one slice of blocks writes it) ----
    if (blockIdx.x == 0 && blockIdx.z == 0) {
        if (mask_mode == 0) {
            float* maskp = out + BN * JN * CN * chw + bj * max_w;
            for (int k = threadIdx.x; k < max_w; k += blockDim.x)
                __stcg(maskp + k, (k < width) ? 1.0f : 0.0f);
        } else if (mask_mode == 1) {
            unsigned char* maskp =
                (unsigned char*)(out + BN * JN * CN * chw) + bj * max_w;
            for (int k = threadIdx.x; k < max_w; k += blockDim.x)
                maskp[k] = (k < width) ? (unsigned char)1 : (unsigned char)0;
        }
    }

    const int idx = blockIdx.x * blockDim.x + threadIdx.x;   // over HT*max_w
    if (idx >= chw) return;

    // i = idx / max_w, k = idx % max_w via float reciprocal + exact fixup
    int i = (int)((float)idx * inv_w);
    int k = idx - i * max_w;
    if (k < 0)           { i--; k += max_w; }
    else if (k >= max_w) { i++; k -= max_w; }

    float* op = outb + idx;                   // == outb + i*max_w + k

    if (k >= width) {
        // masked region -> zeros (buffer poisoned, must write); coalesced per warp
        float* o = op;
        #pragma unroll
        for (int c = 0; c < CG; c++) { __stcg(o, 0.0f); o += chw; }
        return;
    }

    float x = (float)k * each_w + l;
    float y = (float)i * each_h + t;

    float fx = floorf(x), fy = floorf(y);
    int x0 = min(max((int)fx,     0), WIMG_ - 1);
    int x1 = min(max((int)fx + 1, 0), WIMG_ - 1);
    int y0 = min(max((int)fy,     0), HIMG_ - 1);
    int y1 = min(max((int)fy + 1, 0), HIMG_ - 1);

    float wx0 = x - (float)x0;     // weight for x1 side
    float wx1 = (float)x1 - x;     // weight for x0 side
    float wy0 = y - (float)y0;
    float wy1 = (float)y1 - y;

    float wa = wx1 * wy1;   // (y0,x0)
    float wb = wx1 * wy0;   // (y1,x0)
    float wc = wx0 * wy1;   // (y0,x1)
    float wd = wx0 * wy0;   // (y1,x1)

    const int o00 = y0 * WIMG_ + x0;
    const int o01 = y0 * WIMG_ + x1;
    const int o10 = y1 * WIMG_ + x0;
    const int o11 = y1 * WIMG_ + x1;

    const float* ip = imgb;
    float* o = op;
    #pragma unroll
    for (int c = 0; c < CG; c++) {
        float v = __ldg(ip + o00) * wa
                + __ldg(ip + o10) * wb
                + __ldg(ip + o01) * wc
                + __ldg(ip + o11) * wd;
        __stcg(o, v);
        ip += HW;
        o  += chw;
    }
}

extern "C" void kernel_launch(void* const* d_in, const int* in_sizes, int n_in,
                              void* d_out, int out_size)
{
    const float* image = (const float*)d_in[0];
    const float* boxes = (const float*)d_in[1];
    float* out = (float*)d_out;

    // Derive max_w from out_size (host-side, no sync needed).
    const long long per_res = (long long)BN * JN * CN * HT;     // 131072
    const long long per_fmask = per_res + (long long)BN * JN;   // 131584 (float mask)
    const long long per_u8 = per_res + (long long)BN * JN / 4;  // 131200 (u8 mask)

    int max_w, mask_mode;
    long long osz = (long long)out_size;
    if (osz % per_fmask == 0) {
        max_w = (int)(osz / per_fmask);
        mask_mode = 0;
    } else if (osz % per_u8 == 0) {
        max_w = (int)(osz / per_u8);
        mask_mode = 1;
    } else if (osz % per_res == 0) {
        max_w = (int)(osz / per_res);
        mask_mode = 2;
    } else {
        max_w = (int)(osz / per_fmask);
        mask_mode = 0;
    }

    const int block = 256;
    int slices = (HT * max_w + block - 1) / block;
    dim3 grid(slices, BN * JN, CN / CG);
    float inv_w = 1.0f / (float)max_w;
    roirotate_kernel<<<grid, block>>>(image, boxes, out, max_w, inv_w, mask_mode);
}